// round 2
// baseline (speedup 1.0000x reference)
#include <cuda_runtime.h>
#include <cuda_bf16.h>
#include <cstddef>

// ---------------- scratch (no cudaMalloc allowed) ----------------
__device__ float g_anorm[4 * 64 * 64];
__device__ float g_feat1[256 * 16 * 4096];   // [256][16][16][16][16]
__device__ float g_feat2[256 * 2048];        // [256][32*64] == [4][64][2048]
__device__ float g_g1[4 * 64 * 1024];
__device__ float g_g2[4 * 64 * 512];
__device__ float g_g3[4 * 64 * 256];

#define NEG_BIG (-3.402823466e38f)

// ---------------- A_norm: D^-1/2 (A+I) D^-1/2 ----------------
__global__ void anorm_kernel(const int* __restrict__ adj, float* __restrict__ Anorm) {
    __shared__ float dinv[64];
    int b = blockIdx.x, i = threadIdx.x;
    const int* row = adj + (b * 64 + i) * 64;
    int deg = 1;
    for (int j = 0; j < 64; j++) deg += (row[j] != 0);
    dinv[i] = rsqrtf((float)deg);
    __syncthreads();
    float di = dinv[i];
    float* orow = Anorm + (b * 64 + i) * 64;
    for (int j = 0; j < 64; j++) {
        float a = (i == j || row[j] != 0) ? 1.0f : 0.0f;
        orow[j] = a * di * dinv[j];
    }
}

// ---------------- conv1(3x3x3,s1,p1)+bias+relu + maxpool(3,s2,p1) ----------------
// in:  x [256][32][32][32] (1 ch), w [16][27], bias[16]
// out: feat1 [256][16][16][16][16]
// block: (image n, z-group zg of 4 pooled z). 256 threads.
#define C1_IN_SZ   (11 * 32 * 33)
#define C1_CV_SZ   (9 * 32 * 33)
#define C1_SMEM_B  ((C1_IN_SZ + C1_CV_SZ + 448) * 4)

__global__ void conv1_pool_kernel(const float* __restrict__ x,
                                  const float* __restrict__ w,
                                  const float* __restrict__ bias,
                                  float* __restrict__ out) {
    extern __shared__ float smem[];
    float* in_slab   = smem;                 // [11][32][33]
    float* conv_slab = smem + C1_IN_SZ;      // [9][32][33]
    float* ws        = conv_slab + C1_CV_SZ; // [432]
    float* bs        = ws + 432;             // [16]

    const int n  = blockIdx.x;
    const int zg = blockIdx.y;
    const int tid = threadIdx.x;

    for (int i = tid; i < 432; i += 256) ws[i] = w[i];
    if (tid < 16) bs[tid] = bias[tid];

    const float* xin = x + (size_t)n * 32768;
    const int z0 = 8 * zg - 2;
    for (int i = tid; i < 11 * 1024; i += 256) {
        int zz = i >> 10;
        int rem = i & 1023;
        int yy = rem >> 5;
        int xx = rem & 31;
        int gz = z0 + zz;
        float v = (gz >= 0 && gz < 32) ? xin[gz * 1024 + rem] : 0.0f;
        in_slab[zz * (32 * 33) + yy * 33 + xx] = v;
    }
    __syncthreads();

    for (int c = 0; c < 16; c++) {
        float wr[27];
#pragma unroll
        for (int i = 0; i < 27; i++) wr[i] = ws[c * 27 + i];
        float bc = bs[c];

        // conv: 9 z-slices x 32 y x 4 strips of 8 x
        for (int s = tid; s < 9 * 32 * 4; s += 256) {
            int slice = s >> 7;
            int rem = s & 127;
            int y  = rem >> 2;
            int x0 = (rem & 3) << 3;
            int cz = 8 * zg - 1 + slice;
            float* crow = conv_slab + slice * (32 * 33) + y * 33 + x0;
            if (cz >= 0) {  // cz <= 31 always
                float acc[8];
#pragma unroll
                for (int j = 0; j < 8; j++) acc[j] = 0.0f;
#pragma unroll
                for (int kz = 0; kz < 3; kz++) {
                    const float* zbase = in_slab + (slice + kz) * (32 * 33);
#pragma unroll
                    for (int ky = 0; ky < 3; ky++) {
                        int iy = y - 1 + ky;
                        if (iy < 0 || iy > 31) continue;
                        const float* rrow = zbase + iy * 33;
                        float r[10];
#pragma unroll
                        for (int i = 0; i < 10; i++) {
                            int ix = x0 - 1 + i;
                            r[i] = (ix >= 0 && ix < 32) ? rrow[ix] : 0.0f;
                        }
#pragma unroll
                        for (int kx = 0; kx < 3; kx++) {
                            float wv = wr[kz * 9 + ky * 3 + kx];
#pragma unroll
                            for (int j = 0; j < 8; j++)
                                acc[j] += wv * r[j + kx];
                        }
                    }
                }
#pragma unroll
                for (int j = 0; j < 8; j++)
                    crow[j] = fmaxf(acc[j] + bc, 0.0f);
            } else {
#pragma unroll
                for (int j = 0; j < 8; j++) crow[j] = NEG_BIG;
            }
        }
        __syncthreads();

        // pool: 4 x 16 x 16 pooled points
        for (int p = tid; p < 1024; p += 256) {
            int pzl = p >> 8;
            int py = (p >> 4) & 15;
            int px = p & 15;
            float m = NEG_BIG;
#pragma unroll
            for (int dz = 0; dz < 3; dz++) {
                const float* cb = conv_slab + (2 * pzl + dz) * (32 * 33);
#pragma unroll
                for (int dy = 0; dy < 3; dy++) {
                    int yy = 2 * py - 1 + dy;
                    if (yy < 0 || yy > 31) continue;
#pragma unroll
                    for (int dx = 0; dx < 3; dx++) {
                        int xx = 2 * px - 1 + dx;
                        if (xx < 0 || xx > 31) continue;
                        m = fmaxf(m, cb[yy * 33 + xx]);
                    }
                }
            }
            int pz = 4 * zg + pzl;
            out[(((size_t)n * 16 + c) * 16 + pz) * 256 + py * 16 + px] = m;
        }
        __syncthreads();
    }
}

// ---------------- conv2(3x3x3,s2,p1,16->32)+bias+relu + maxpool(3,s2,p1) ----------------
// in: feat1 [256][16][4096]; w [32][16][27] -> transposed smem [(ic*27+k)][32]
// out: feat2 [256][2048]  (== [256][32 ch][64 spatial])
#define C2_SMEM_B ((13824 + 32 * 512) * 4)

__global__ void conv2_pool_kernel(const float* __restrict__ feat1,
                                  const float* __restrict__ w,
                                  const float* __restrict__ bias,
                                  float* __restrict__ out) {
    extern __shared__ float smem[];
    float* wts   = smem;          // [432][32] transposed
    float* convs = smem + 13824;  // [32][512]

    const int n = blockIdx.x;
    const int t = threadIdx.x;  // 512 threads

    for (int i = t; i < 13824; i += 512) {
        int oc = i / 432;
        int rem = i - oc * 432;
        wts[rem * 32 + oc] = w[i];
    }
    __syncthreads();

    const int oz = t >> 6, oy = (t >> 3) & 7, ox = t & 7;
    const float* in = feat1 + (size_t)n * 16 * 4096;

    float acc[32];
#pragma unroll
    for (int oc = 0; oc < 32; oc++) acc[oc] = 0.0f;

    for (int ic = 0; ic < 16; ic++) {
        const float* inc = in + ic * 4096;
#pragma unroll
        for (int kz = 0; kz < 3; kz++) {
            int iz = 2 * oz - 1 + kz;
            if (iz < 0 || iz > 15) continue;
#pragma unroll
            for (int ky = 0; ky < 3; ky++) {
                int iy = 2 * oy - 1 + ky;
                if (iy < 0 || iy > 15) continue;
#pragma unroll
                for (int kx = 0; kx < 3; kx++) {
                    int ix = 2 * ox - 1 + kx;
                    if (ix < 0 || ix > 15) continue;
                    float v = inc[iz * 256 + iy * 16 + ix];
                    const float4* wp =
                        (const float4*)(wts + (ic * 27 + kz * 9 + ky * 3 + kx) * 32);
#pragma unroll
                    for (int q = 0; q < 8; q++) {
                        float4 w4 = wp[q];
                        acc[q * 4 + 0] += v * w4.x;
                        acc[q * 4 + 1] += v * w4.y;
                        acc[q * 4 + 2] += v * w4.z;
                        acc[q * 4 + 3] += v * w4.w;
                    }
                }
            }
        }
    }
#pragma unroll
    for (int oc = 0; oc < 32; oc++)
        convs[oc * 512 + t] = fmaxf(acc[oc] + bias[oc], 0.0f);
    __syncthreads();

    for (int p = t; p < 2048; p += 512) {
        int oc = p >> 6;
        int pz = (p >> 4) & 3, py = (p >> 2) & 3, px = p & 3;
        const float* cb = convs + oc * 512;
        float m = NEG_BIG;
#pragma unroll
        for (int dz = 0; dz < 3; dz++) {
            int zz = 2 * pz - 1 + dz; if (zz < 0 || zz > 7) continue;
#pragma unroll
            for (int dy = 0; dy < 3; dy++) {
                int yy = 2 * py - 1 + dy; if (yy < 0 || yy > 7) continue;
#pragma unroll
                for (int dx = 0; dx < 3; dx++) {
                    int xx = 2 * px - 1 + dx; if (xx < 0 || xx > 7) continue;
                    m = fmaxf(m, cb[zz * 64 + yy * 8 + xx]);
                }
            }
        }
        out[(size_t)n * 2048 + p] = m;
    }
}

// ---------------- GCN layer: out = maybe_relu(A @ (X@W) + bias) ----------------
// BM = 64 (whole graph), BN = 64, BK = 32. 256 threads, 4x4 micro-tile.
template <int K, int F, bool RELU>
__global__ void gcn_layer_kernel(const float* __restrict__ X,     // [B*64,K]
                                 const float* __restrict__ W,     // [K,F]
                                 const float* __restrict__ bias,  // [F]
                                 const float* __restrict__ Anorm, // [B,64,64]
                                 float* __restrict__ out) {       // [B*64,F]
    __shared__ float sm[64 * 65 + 64 * 64];
    float* Xs = sm;            // [32][65]
    float* Ws = sm + 32 * 65;  // [32][64]
    float* Cs = sm;            // [64][65] (reused after sync)
    float* As = sm + 64 * 65;  // [64][64]

    const int b  = blockIdx.y;
    const int f0 = blockIdx.x * 64;
    const int t  = threadIdx.x;
    const int ty = t >> 4, tx = t & 15;

    float acc[4][4];
#pragma unroll
    for (int i = 0; i < 4; i++)
#pragma unroll
        for (int j = 0; j < 4; j++) acc[i][j] = 0.f;

    const float* Xb = X + (size_t)b * 64 * K;

    for (int k0 = 0; k0 < K; k0 += 32) {
#pragma unroll
        for (int e = 0; e < 8; e++) {
            int idx = t + e * 256;
            int row = idx >> 5, kk = idx & 31;
            Xs[kk * 65 + row] = Xb[(size_t)row * K + k0 + kk];
        }
#pragma unroll
        for (int e = 0; e < 8; e++) {
            int idx = t + e * 256;
            int kk = idx >> 6, c = idx & 63;
            Ws[kk * 64 + c] = W[(size_t)(k0 + kk) * F + f0 + c];
        }
        __syncthreads();
#pragma unroll
        for (int kk = 0; kk < 32; kk++) {
            float a[4], bb[4];
#pragma unroll
            for (int i = 0; i < 4; i++) a[i] = Xs[kk * 65 + ty + 16 * i];
#pragma unroll
            for (int j = 0; j < 4; j++) bb[j] = Ws[kk * 64 + tx + 16 * j];
#pragma unroll
            for (int i = 0; i < 4; i++)
#pragma unroll
                for (int j = 0; j < 4; j++) acc[i][j] += a[i] * bb[j];
        }
        __syncthreads();
    }

    // stash C tile, load A, apply A-mult epilogue
#pragma unroll
    for (int i = 0; i < 4; i++)
#pragma unroll
        for (int j = 0; j < 4; j++)
            Cs[(ty + 16 * i) * 65 + tx + 16 * j] = acc[i][j];
    const float* Ab = Anorm + b * 4096;
#pragma unroll
    for (int e = 0; e < 16; e++) As[t + e * 256] = Ab[t + e * 256];
    __syncthreads();

    float y[4][4];
#pragma unroll
    for (int i = 0; i < 4; i++)
#pragma unroll
        for (int j = 0; j < 4; j++) y[i][j] = 0.f;
    for (int jj = 0; jj < 64; jj++) {
        float av[4], cv[4];
#pragma unroll
        for (int i = 0; i < 4; i++) av[i] = As[(ty + 16 * i) * 64 + jj];
#pragma unroll
        for (int j = 0; j < 4; j++) cv[j] = Cs[jj * 65 + tx + 16 * j];
#pragma unroll
        for (int i = 0; i < 4; i++)
#pragma unroll
            for (int j = 0; j < 4; j++) y[i][j] += av[i] * cv[j];
    }
#pragma unroll
    for (int j = 0; j < 4; j++) {
        float bv = bias[f0 + tx + 16 * j];
#pragma unroll
        for (int i = 0; i < 4; i++) {
            float v = y[i][j] + bv;
            if (RELU) v = fmaxf(v, 0.f);
            out[(size_t)(b * 64 + ty + 16 * i) * F + f0 + tx + 16 * j] = v;
        }
    }
}

// ---------------- head: maxpool1d(64) + fc1 + relu + fc2 + softmax ----------------
__global__ void head_kernel(const float* __restrict__ g3,  // [4,64,256]
                            const float* __restrict__ w1,  // [256,512]
                            const float* __restrict__ b1,  // [512]
                            const float* __restrict__ w2,  // [512,4]
                            const float* __restrict__ b2,  // [4]
                            float* __restrict__ outp) {    // [4,4]
    __shared__ float pooled[1024];  // [4][256]
    __shared__ float h1[2048];      // [4][512]
    __shared__ float logits[16];
    const int t = threadIdx.x;  // 256

    for (int p = t; p < 1024; p += 256) {
        int b = p >> 8;
        int i = p & 255;
        int node = i >> 2;
        int fbase = (i & 3) << 6;
        const float* src = g3 + ((size_t)b * 64 + node) * 256 + fbase;
        float m = src[0];
#pragma unroll
        for (int j = 1; j < 64; j++) m = fmaxf(m, src[j]);
        pooled[p] = m;
    }
    __syncthreads();
    for (int q = t; q < 2048; q += 256) {
        int b = q >> 9;
        int o = q & 511;
        const float* pb = pooled + b * 256;
        float s = b1[o];
        for (int k = 0; k < 256; k++) s += pb[k] * w1[k * 512 + o];
        h1[q] = fmaxf(s, 0.f);
    }
    __syncthreads();
    if (t < 16) {
        int b = t >> 2, o = t & 3;
        const float* hb = h1 + b * 512;
        float s = b2[o];
        for (int k = 0; k < 512; k++) s += hb[k] * w2[k * 4 + o];
        logits[t] = s;
    }
    __syncthreads();
    if (t < 4) {
        float mx = logits[t * 4];
        for (int j = 1; j < 4; j++) mx = fmaxf(mx, logits[t * 4 + j]);
        float e[4], ssum = 0.f;
        for (int j = 0; j < 4; j++) { e[j] = expf(logits[t * 4 + j] - mx); ssum += e[j]; }
        for (int j = 0; j < 4; j++) outp[t * 4 + j] = e[j] / ssum;
    }
}

// ---------------- launch ----------------
extern "C" void kernel_launch(void* const* d_in, const int* in_sizes, int n_in,
                              void* d_out, int out_size) {
    const float* x    = (const float*)d_in[0];
    const int*   adj  = (const int*)d_in[1];
    // d_in[2] = batch_size scalar (shapes hardcoded)
    const float* w_c1 = (const float*)d_in[3];
    const float* b_c1 = (const float*)d_in[4];
    const float* w_c2 = (const float*)d_in[5];
    const float* b_c2 = (const float*)d_in[6];
    const float* w_g1 = (const float*)d_in[7];
    const float* b_g1 = (const float*)d_in[8];
    const float* w_g2 = (const float*)d_in[9];
    const float* b_g2 = (const float*)d_in[10];
    const float* w_g3 = (const float*)d_in[11];
    const float* b_g3 = (const float*)d_in[12];
    const float* w_f1 = (const float*)d_in[13];
    const float* b_f1 = (const float*)d_in[14];
    const float* w_f2 = (const float*)d_in[15];
    const float* b_f2 = (const float*)d_in[16];

    void *p_anorm, *p_feat1, *p_feat2, *p_g1, *p_g2, *p_g3;
    cudaGetSymbolAddress(&p_anorm, g_anorm);
    cudaGetSymbolAddress(&p_feat1, g_feat1);
    cudaGetSymbolAddress(&p_feat2, g_feat2);
    cudaGetSymbolAddress(&p_g1, g_g1);
    cudaGetSymbolAddress(&p_g2, g_g2);
    cudaGetSymbolAddress(&p_g3, g_g3);

    cudaFuncSetAttribute(conv1_pool_kernel,
                         cudaFuncAttributeMaxDynamicSharedMemorySize, C1_SMEM_B);
    cudaFuncSetAttribute(conv2_pool_kernel,
                         cudaFuncAttributeMaxDynamicSharedMemorySize, C2_SMEM_B);

    anorm_kernel<<<4, 64>>>(adj, (float*)p_anorm);
    conv1_pool_kernel<<<dim3(256, 4), 256, C1_SMEM_B>>>(x, w_c1, b_c1, (float*)p_feat1);
    conv2_pool_kernel<<<256, 512, C2_SMEM_B>>>((const float*)p_feat1, w_c2, b_c2,
                                               (float*)p_feat2);
    gcn_layer_kernel<2048, 1024, true><<<dim3(16, 4), 256>>>(
        (const float*)p_feat2, w_g1, b_g1, (const float*)p_anorm, (float*)p_g1);
    gcn_layer_kernel<1024, 512, true><<<dim3(8, 4), 256>>>(
        (const float*)p_g1, w_g2, b_g2, (const float*)p_anorm, (float*)p_g2);
    gcn_layer_kernel<512, 256, false><<<dim3(4, 4), 256>>>(
        (const float*)p_g2, w_g3, b_g3, (const float*)p_anorm, (float*)p_g3);
    head_kernel<<<1, 256>>>((const float*)p_g3, w_f1, b_f1, w_f2, b_f2, (float*)d_out);
}

// round 3
// speedup vs baseline: 1.4859x; 1.4859x over previous
#include <cuda_runtime.h>
#include <cuda_bf16.h>
#include <cstddef>

// ---------------- scratch (no cudaMalloc allowed) ----------------
__device__ float g_anorm[4 * 64 * 64];
__device__ float g_feat1[256 * 16 * 4096];   // [256][16][16][16][16]
__device__ float g_feat2[256 * 2048];        // [256][2048] == [4][64][2048]
__device__ float g_part[1 << 20];            // split-K partials (max 4MB)
__device__ float g_g1[4 * 64 * 1024];
__device__ float g_g2[4 * 64 * 512];
__device__ float g_g3[4 * 64 * 256];

#define NEG_BIG (-3.402823466e38f)

// ---------------- packed f32x2 helpers ----------------
__device__ __forceinline__ unsigned long long pack2(float lo, float hi) {
    unsigned long long r;
    asm("mov.b64 %0, {%1, %2};" : "=l"(r) : "f"(lo), "f"(hi));
    return r;
}
__device__ __forceinline__ void fma2(unsigned long long& d,
                                     unsigned long long a, unsigned long long b) {
    asm("fma.rn.f32x2 %0, %1, %2, %0;" : "+l"(d) : "l"(a), "l"(b));
}
__device__ __forceinline__ float2 unpack2(unsigned long long v) {
    float2 f;
    asm("mov.b64 {%0, %1}, %2;" : "=f"(f.x), "=f"(f.y) : "l"(v));
    return f;
}

// ---------------- A_norm: D^-1/2 (A+I) D^-1/2 ----------------
__global__ void anorm_kernel(const int* __restrict__ adj, float* __restrict__ Anorm) {
    __shared__ float dinv[64];
    int b = blockIdx.x, i = threadIdx.x;
    const int* row = adj + (b * 64 + i) * 64;
    int deg = 1;
    for (int j = 0; j < 64; j++) deg += (row[j] != 0);
    dinv[i] = rsqrtf((float)deg);
    __syncthreads();
    float di = dinv[i];
    float* orow = Anorm + (b * 64 + i) * 64;
    for (int j = 0; j < 64; j++) {
        float a = (i == j || row[j] != 0) ? 1.0f : 0.0f;
        orow[j] = a * di * dinv[j];
    }
}

// ---------------- conv1(3x3x3,s1,p1)+bias+relu + maxpool(3,s2,p1) ----------------
// padded slabs (34x34) -> branch-free inner loops; f32x2 packed FMAs.
#define C1_IN_SZ   (11 * 34 * 34)     // 12716
#define C1_CV_SZ   (9 * 34 * 34)      // 10404
#define C1_SMEM_B  ((C1_IN_SZ + C1_CV_SZ + 448) * 4)

__global__ void conv1_pool_kernel(const float* __restrict__ x,
                                  const float* __restrict__ w,
                                  const float* __restrict__ bias,
                                  float* __restrict__ out) {
    extern __shared__ float smem[];
    float* in_slab   = smem;                 // [11][34][34], zero-padded borders
    float* conv_slab = smem + C1_IN_SZ;      // [9][34][34], NEG_BIG borders
    float* ws        = conv_slab + C1_CV_SZ; // [432]
    float* bs        = ws + 432;             // [16]

    const int n  = blockIdx.x;
    const int zg = blockIdx.y;
    const int tid = threadIdx.x;

    for (int i = tid; i < 432; i += 256) ws[i] = w[i];
    if (tid < 16) bs[tid] = bias[tid];
    for (int i = tid; i < C1_IN_SZ; i += 256) in_slab[i] = 0.0f;
    for (int i = tid; i < C1_CV_SZ; i += 256) conv_slab[i] = NEG_BIG;
    __syncthreads();

    const float* xin = x + (size_t)n * 32768;
    const int z0 = 8 * zg - 2;
    for (int i = tid; i < 11 * 1024; i += 256) {
        int zz = i >> 10;
        int rem = i & 1023;
        int yy = rem >> 5;
        int xx = rem & 31;
        int gz = z0 + zz;
        float v = (gz >= 0 && gz < 32) ? xin[gz * 1024 + rem] : 0.0f;
        in_slab[zz * 1156 + (yy + 1) * 34 + xx + 1] = v;
    }
    __syncthreads();

    for (int c = 0; c < 16; c++) {
        float wr[27];
#pragma unroll
        for (int i = 0; i < 27; i++) wr[i] = ws[c * 27 + i];
        float bc = bs[c];

        // conv: 9 z-slices x 32 y x 4 strips of 8 x
        for (int s = tid; s < 9 * 32 * 4; s += 256) {
            int slice = s >> 7;
            int rem = s & 127;
            int y  = rem >> 2;
            int x0 = (rem & 3) << 3;
            int cz = 8 * zg - 1 + slice;
            float* crow = conv_slab + slice * 1156 + (y + 1) * 34 + (x0 + 1);
            if (cz >= 0) {  // cz <= 31 always
                unsigned long long A[4];
#pragma unroll
                for (int j = 0; j < 4; j++) A[j] = 0ull;
#pragma unroll
                for (int kz = 0; kz < 3; kz++) {
                    const float* zbase = in_slab + (slice + kz) * 1156;
#pragma unroll
                    for (int ky = 0; ky < 3; ky++) {
                        const float* rrow = zbase + (y + ky) * 34 + x0;
                        float r[10];
#pragma unroll
                        for (int i = 0; i < 10; i++) r[i] = rrow[i];
                        unsigned long long e0 = pack2(r[0], r[1]);
                        unsigned long long e1 = pack2(r[2], r[3]);
                        unsigned long long e2 = pack2(r[4], r[5]);
                        unsigned long long e3 = pack2(r[6], r[7]);
                        unsigned long long e4 = pack2(r[8], r[9]);
                        unsigned long long o0 = pack2(r[1], r[2]);
                        unsigned long long o1 = pack2(r[3], r[4]);
                        unsigned long long o2 = pack2(r[5], r[6]);
                        unsigned long long o3 = pack2(r[7], r[8]);
                        float w0 = wr[kz * 9 + ky * 3 + 0];
                        float w1 = wr[kz * 9 + ky * 3 + 1];
                        float w2 = wr[kz * 9 + ky * 3 + 2];
                        unsigned long long W0 = pack2(w0, w0);
                        unsigned long long W1 = pack2(w1, w1);
                        unsigned long long W2 = pack2(w2, w2);
                        fma2(A[0], W0, e0); fma2(A[1], W0, e1);
                        fma2(A[2], W0, e2); fma2(A[3], W0, e3);
                        fma2(A[0], W1, o0); fma2(A[1], W1, o1);
                        fma2(A[2], W1, o2); fma2(A[3], W1, o3);
                        fma2(A[0], W2, e1); fma2(A[1], W2, e2);
                        fma2(A[2], W2, e3); fma2(A[3], W2, e4);
                    }
                }
#pragma unroll
                for (int j = 0; j < 4; j++) {
                    float2 p = unpack2(A[j]);
                    crow[2 * j]     = fmaxf(p.x + bc, 0.0f);
                    crow[2 * j + 1] = fmaxf(p.y + bc, 0.0f);
                }
            } else {
#pragma unroll
                for (int j = 0; j < 8; j++) crow[j] = NEG_BIG;
            }
        }
        __syncthreads();

        // pool: 4 x 16 x 16 pooled points, branch-free via pads
        for (int p = tid; p < 1024; p += 256) {
            int pzl = p >> 8;
            int py = (p >> 4) & 15;
            int px = p & 15;
            float m = NEG_BIG;
#pragma unroll
            for (int dz = 0; dz < 3; dz++) {
                const float* cb = conv_slab + (2 * pzl + dz) * 1156;
#pragma unroll
                for (int dy = 0; dy < 3; dy++) {
#pragma unroll
                    for (int dx = 0; dx < 3; dx++) {
                        m = fmaxf(m, cb[(2 * py + dy) * 34 + 2 * px + dx]);
                    }
                }
            }
            int pz = 4 * zg + pzl;
            out[(((size_t)n * 16 + c) * 16 + pz) * 256 + py * 16 + px] = m;
        }
        __syncthreads();
    }
}

// ---------------- conv2(3x3x3,s2,p1,16->32)+bias+relu + maxpool(3,s2,p1) ----------------
#define C2_SMEM_B ((13824 + 32 * 512) * 4)

__global__ void conv2_pool_kernel(const float* __restrict__ feat1,
                                  const float* __restrict__ w,
                                  const float* __restrict__ bias,
                                  float* __restrict__ out) {
    extern __shared__ float smem[];
    float* wts   = smem;          // [432][32] transposed (oc pairs adjacent)
    float* convs = smem + 13824;  // [32][512]

    const int n = blockIdx.x;
    const int t = threadIdx.x;  // 512 threads

    for (int i = t; i < 13824; i += 512) {
        int oc = i / 432;
        int rem = i - oc * 432;
        wts[rem * 32 + oc] = w[i];
    }
    __syncthreads();

    const int oz = t >> 6, oy = (t >> 3) & 7, ox = t & 7;
    const float* in = feat1 + (size_t)n * 16 * 4096;

    unsigned long long accp[16];
#pragma unroll
    for (int q = 0; q < 16; q++) accp[q] = 0ull;

    for (int ic = 0; ic < 16; ic++) {
        const float* inc = in + ic * 4096;
#pragma unroll
        for (int kz = 0; kz < 3; kz++) {
            int iz = 2 * oz - 1 + kz;
            if (iz < 0 || iz > 15) continue;
#pragma unroll
            for (int ky = 0; ky < 3; ky++) {
                int iy = 2 * oy - 1 + ky;
                if (iy < 0 || iy > 15) continue;
#pragma unroll
                for (int kx = 0; kx < 3; kx++) {
                    int ix = 2 * ox - 1 + kx;
                    if (ix < 0 || ix > 15) continue;
                    float v = inc[iz * 256 + iy * 16 + ix];
                    unsigned long long vv = pack2(v, v);
                    const ulonglong2* wp =
                        (const ulonglong2*)(wts + (ic * 27 + kz * 9 + ky * 3 + kx) * 32);
#pragma unroll
                    for (int q = 0; q < 8; q++) {
                        ulonglong2 w2 = wp[q];
                        fma2(accp[2 * q],     vv, w2.x);
                        fma2(accp[2 * q + 1], vv, w2.y);
                    }
                }
            }
        }
    }
#pragma unroll
    for (int q = 0; q < 16; q++) {
        float2 p = unpack2(accp[q]);
        convs[(2 * q) * 512 + t]     = fmaxf(p.x + bias[2 * q], 0.0f);
        convs[(2 * q + 1) * 512 + t] = fmaxf(p.y + bias[2 * q + 1], 0.0f);
    }
    __syncthreads();

    for (int p = t; p < 2048; p += 512) {
        int oc = p >> 6;
        int pz = (p >> 4) & 3, py = (p >> 2) & 3, px = p & 3;
        const float* cb = convs + oc * 512;
        float m = NEG_BIG;
#pragma unroll
        for (int dz = 0; dz < 3; dz++) {
            int zz = 2 * pz - 1 + dz; if (zz < 0 || zz > 7) continue;
#pragma unroll
            for (int dy = 0; dy < 3; dy++) {
                int yy = 2 * py - 1 + dy; if (yy < 0 || yy > 7) continue;
#pragma unroll
                for (int dx = 0; dx < 3; dx++) {
                    int xx = 2 * px - 1 + dx; if (xx < 0 || xx > 7) continue;
                    m = fmaxf(m, cb[zz * 64 + yy * 8 + xx]);
                }
            }
        }
        out[(size_t)n * 2048 + p] = m;
    }
}

// ---------------- split-K GEMM: P[s] = X[:, sKc:(s+1)Kc] @ W[sKc:(s+1)Kc, :] ----------------
// 64x64 tile, 256 threads, 4x4 microtile with f32x2 packed FMAs.
template <int K, int F, int Kc>
__global__ void gemm_splitk(const float* __restrict__ X,   // [256,K]
                            const float* __restrict__ W,   // [K,F]
                            float* __restrict__ P) {       // [S,256,F]
    __shared__ __align__(16) float Xs[32 * 64];  // [kk][row]
    __shared__ __align__(16) float Ws[32 * 64];  // [kk][col]

    const int f0 = blockIdx.x * 64;
    const int r0 = blockIdx.y * 64;
    const int s  = blockIdx.z;
    const int t  = threadIdx.x;
    const int ty = t >> 4, tx = t & 15;
    const int k0base = s * Kc;

    unsigned long long acc[4][2];
#pragma unroll
    for (int i = 0; i < 4; i++) { acc[i][0] = 0ull; acc[i][1] = 0ull; }

    const int xrow = t >> 2;          // 0..63
    const int xk0  = (t & 3) * 8;     // 0,8,16,24
    const int wkk  = t >> 3;          // 0..31
    const int wc4  = (t & 7) * 8;     // 0..56

    for (int k0 = k0base; k0 < k0base + Kc; k0 += 32) {
        {
            const float* xp = X + (size_t)(r0 + xrow) * K + k0 + xk0;
            float4 v0 = *(const float4*)xp;
            float4 v1 = *(const float4*)(xp + 4);
            Xs[(xk0 + 0) * 64 + xrow] = v0.x;
            Xs[(xk0 + 1) * 64 + xrow] = v0.y;
            Xs[(xk0 + 2) * 64 + xrow] = v0.z;
            Xs[(xk0 + 3) * 64 + xrow] = v0.w;
            Xs[(xk0 + 4) * 64 + xrow] = v1.x;
            Xs[(xk0 + 5) * 64 + xrow] = v1.y;
            Xs[(xk0 + 6) * 64 + xrow] = v1.z;
            Xs[(xk0 + 7) * 64 + xrow] = v1.w;
        }
        {
            const float* wp = W + (size_t)(k0 + wkk) * F + f0 + wc4;
            *(float4*)&Ws[wkk * 64 + wc4]     = *(const float4*)wp;
            *(float4*)&Ws[wkk * 64 + wc4 + 4] = *(const float4*)(wp + 4);
        }
        __syncthreads();
#pragma unroll
        for (int kk = 0; kk < 32; kk++) {
            float4 a4 = *(const float4*)&Xs[kk * 64 + ty * 4];
            ulonglong2 b2 = *(const ulonglong2*)&Ws[kk * 64 + tx * 4];
            unsigned long long a0 = pack2(a4.x, a4.x);
            unsigned long long a1 = pack2(a4.y, a4.y);
            unsigned long long a2 = pack2(a4.z, a4.z);
            unsigned long long a3 = pack2(a4.w, a4.w);
            fma2(acc[0][0], a0, b2.x); fma2(acc[0][1], a0, b2.y);
            fma2(acc[1][0], a1, b2.x); fma2(acc[1][1], a1, b2.y);
            fma2(acc[2][0], a2, b2.x); fma2(acc[2][1], a2, b2.y);
            fma2(acc[3][0], a3, b2.x); fma2(acc[3][1], a3, b2.y);
        }
        __syncthreads();
    }

    float* Pp = P + ((size_t)s * 256 + r0) * F + f0;
#pragma unroll
    for (int i = 0; i < 4; i++) {
        float2 p0 = unpack2(acc[i][0]);
        float2 p1 = unpack2(acc[i][1]);
        float* orow = Pp + (size_t)(ty * 4 + i) * F + tx * 4;
        orow[0] = p0.x; orow[1] = p0.y; orow[2] = p1.x; orow[3] = p1.y;
    }
}

// ---------------- GCN epilogue: out = maybe_relu(A @ (sum_s P[s]) + bias) ----------------
template <int F, int S, bool RELU>
__global__ void gcn_epilogue(const float* __restrict__ P,      // [S,256,F]
                             const float* __restrict__ Anorm,  // [B,64,64]
                             const float* __restrict__ bias,   // [F]
                             float* __restrict__ out) {        // [256,F]
    __shared__ __align__(16) float As[64 * 64];
    __shared__ __align__(16) float Zs[64 * 68];

    const int f0 = blockIdx.x * 64;
    const int b  = blockIdx.y;
    const int t  = threadIdx.x;
    const int ty = t >> 4, tx = t & 15;

    const float* Ab = Anorm + b * 4096;
#pragma unroll
    for (int e = 0; e < 16; e++) As[t + e * 256] = Ab[t + e * 256];

#pragma unroll
    for (int e = 0; e < 16; e++) {
        int idx = t + e * 256;
        int r = idx >> 6, c = idx & 63;
        float z = 0.0f;
#pragma unroll
        for (int s = 0; s < S; s++)
            z += P[((size_t)s * 256 + b * 64 + r) * F + f0 + c];
        Zs[r * 68 + c] = z;
    }
    __syncthreads();

    float y[4][4];
#pragma unroll
    for (int i = 0; i < 4; i++)
#pragma unroll
        for (int j = 0; j < 4; j++) y[i][j] = 0.f;

    for (int jj = 0; jj < 64; jj++) {
        float av[4];
#pragma unroll
        for (int i = 0; i < 4; i++) av[i] = As[(ty * 4 + i) * 64 + jj];
        float4 cv = *(const float4*)&Zs[jj * 68 + tx * 4];
#pragma unroll
        for (int i = 0; i < 4; i++) {
            y[i][0] += av[i] * cv.x;
            y[i][1] += av[i] * cv.y;
            y[i][2] += av[i] * cv.z;
            y[i][3] += av[i] * cv.w;
        }
    }
#pragma unroll
    for (int j = 0; j < 4; j++) {
        float bv = bias[f0 + tx * 4 + j];
#pragma unroll
        for (int i = 0; i < 4; i++) {
            float v = y[i][j] + bv;
            if (RELU) v = fmaxf(v, 0.f);
            out[(size_t)(b * 64 + ty * 4 + i) * F + f0 + tx * 4 + j] = v;
        }
    }
}

// ---------------- head: maxpool1d(64) + fc1 + relu + fc2 + softmax ----------------
__global__ void head_kernel(const float* __restrict__ g3,  // [4,64,256]
                            const float* __restrict__ w1,  // [256,512]
                            const float* __restrict__ b1,  // [512]
                            const float* __restrict__ w2,  // [512,4]
                            const float* __restrict__ b2,  // [4]
                            float* __restrict__ outp) {    // [4,4]
    __shared__ float pooled[1024];  // [4][256]
    __shared__ float h1[2048];      // [4][512]
    __shared__ float logits[16];
    const int t = threadIdx.x;  // 256

    for (int p = t; p < 1024; p += 256) {
        int b = p >> 8;
        int i = p & 255;
        int node = i >> 2;
        int fbase = (i & 3) << 6;
        const float* src = g3 + ((size_t)b * 64 + node) * 256 + fbase;
        float m = src[0];
#pragma unroll
        for (int j = 1; j < 64; j++) m = fmaxf(m, src[j]);
        pooled[p] = m;
    }
    __syncthreads();
    for (int q = t; q < 2048; q += 256) {
        int b = q >> 9;
        int o = q & 511;
        const float* pb = pooled + b * 256;
        float s = b1[o];
        for (int k = 0; k < 256; k++) s += pb[k] * w1[k * 512 + o];
        h1[q] = fmaxf(s, 0.f);
    }
    __syncthreads();
    if (t < 16) {
        int b = t >> 2, o = t & 3;
        const float* hb = h1 + b * 512;
        float s = b2[o];
        for (int k = 0; k < 512; k++) s += hb[k] * w2[k * 4 + o];
        logits[t] = s;
    }
    __syncthreads();
    if (t < 4) {
        float mx = logits[t * 4];
        for (int j = 1; j < 4; j++) mx = fmaxf(mx, logits[t * 4 + j]);
        float e[4], ssum = 0.f;
        for (int j = 0; j < 4; j++) { e[j] = expf(logits[t * 4 + j] - mx); ssum += e[j]; }
        for (int j = 0; j < 4; j++) outp[t * 4 + j] = e[j] / ssum;
    }
}

// ---------------- launch ----------------
extern "C" void kernel_launch(void* const* d_in, const int* in_sizes, int n_in,
                              void* d_out, int out_size) {
    const float* x    = (const float*)d_in[0];
    const int*   adj  = (const int*)d_in[1];
    const float* w_c1 = (const float*)d_in[3];
    const float* b_c1 = (const float*)d_in[4];
    const float* w_c2 = (const float*)d_in[5];
    const float* b_c2 = (const float*)d_in[6];
    const float* w_g1 = (const float*)d_in[7];
    const float* b_g1 = (const float*)d_in[8];
    const float* w_g2 = (const float*)d_in[9];
    const float* b_g2 = (const float*)d_in[10];
    const float* w_g3 = (const float*)d_in[11];
    const float* b_g3 = (const float*)d_in[12];
    const float* w_f1 = (const float*)d_in[13];
    const float* b_f1 = (const float*)d_in[14];
    const float* w_f2 = (const float*)d_in[15];
    const float* b_f2 = (const float*)d_in[16];

    void *p_anorm, *p_feat1, *p_feat2, *p_part, *p_g1, *p_g2, *p_g3;
    cudaGetSymbolAddress(&p_anorm, g_anorm);
    cudaGetSymbolAddress(&p_feat1, g_feat1);
    cudaGetSymbolAddress(&p_feat2, g_feat2);
    cudaGetSymbolAddress(&p_part, g_part);
    cudaGetSymbolAddress(&p_g1, g_g1);
    cudaGetSymbolAddress(&p_g2, g_g2);
    cudaGetSymbolAddress(&p_g3, g_g3);

    cudaFuncSetAttribute(conv1_pool_kernel,
                         cudaFuncAttributeMaxDynamicSharedMemorySize, C1_SMEM_B);
    cudaFuncSetAttribute(conv2_pool_kernel,
                         cudaFuncAttributeMaxDynamicSharedMemorySize, C2_SMEM_B);

    anorm_kernel<<<4, 64>>>(adj, (float*)p_anorm);
    conv1_pool_kernel<<<dim3(256, 4), 256, C1_SMEM_B>>>(x, w_c1, b_c1, (float*)p_feat1);
    conv2_pool_kernel<<<256, 512, C2_SMEM_B>>>((const float*)p_feat1, w_c2, b_c2,
                                               (float*)p_feat2);

    // GCN layer 1: [256,2048]x[2048,1024], S=4
    gemm_splitk<2048, 1024, 512><<<dim3(16, 4, 4), 256>>>(
        (const float*)p_feat2, w_g1, (float*)p_part);
    gcn_epilogue<1024, 4, true><<<dim3(16, 4), 256>>>(
        (const float*)p_part, (const float*)p_anorm, b_g1, (float*)p_g1);

    // GCN layer 2: [256,1024]x[1024,512], S=8
    gemm_splitk<1024, 512, 128><<<dim3(8, 4, 8), 256>>>(
        (const float*)p_g1, w_g2, (float*)p_part);
    gcn_epilogue<512, 8, true><<<dim3(8, 4), 256>>>(
        (const float*)p_part, (const float*)p_anorm, b_g2, (float*)p_g2);

    // GCN layer 3: [256,512]x[512,256], S=8
    gemm_splitk<512, 256, 64><<<dim3(4, 4, 8), 256>>>(
        (const float*)p_g2, w_g3, (float*)p_part);
    gcn_epilogue<256, 8, false><<<dim3(4, 4), 256>>>(
        (const float*)p_part, (const float*)p_anorm, b_g3, (float*)p_g3);

    head_kernel<<<1, 256>>>((const float*)p_g3, w_f1, b_f1, w_f2, b_f2, (float*)d_out);
}